// round 1
// baseline (speedup 1.0000x reference)
#include <cuda_runtime.h>

// Local covariance: out = boxmean5( (center(x)-boxmean5(x)) * (center(y)-boxmean5(y)) )
// x,y: [16,1,1024,1024] f32 -> out: [16,1,1016,1016] f32
// Fully fused, tiled, separable sliding-window box sums in shared memory.

#define TILE 32
#define IN   40   // TILE + 8 (two 5x5 valid convs -> 8 halo)
#define MID  36   // TILE + 4
#define H 1024
#define W 1024
#define OH 1016
#define OW 1016
#define NB 16

__global__ __launch_bounds__(256)
void cov_kernel(const float* __restrict__ x,
                const float* __restrict__ y,
                float* __restrict__ out)
{
    __shared__ float sx[IN][IN + 1];     // raw x tile      (stride 41, odd -> conflict free)
    __shared__ float sy[IN][IN + 1];     // raw y tile
    __shared__ float hx[IN][MID + 1];    // horizontal 5-sums of x (stride 37)
    __shared__ float hy[IN][MID + 1];
    __shared__ float sp[MID][MID + 1];   // p = xc*yc       (stride 37)
    __shared__ float hp[MID][TILE + 1];  // horizontal 5-sums of p (stride 33)

    const int tid = threadIdx.x;
    const int i0 = blockIdx.y * TILE;
    const int j0 = blockIdx.x * TILE;
    const long base = (long)blockIdx.z * (long)(H * W);
    const float* xb = x + base;
    const float* yb = y + base;

    // ---- Phase 1: load 40x40 halo tiles of x and y -------------------------
    for (int idx = tid; idx < IN * IN; idx += 256) {
        int r = idx / IN, c = idx - r * IN;
        int gr = i0 + r, gc = j0 + c;
        bool ok = (gr < H) && (gc < W);
        float vx = ok ? __ldg(xb + gr * W + gc) : 0.f;
        float vy = ok ? __ldg(yb + gr * W + gc) : 0.f;
        sx[r][c] = vx;
        sy[r][c] = vy;
    }
    __syncthreads();

    // ---- Phase 2: horizontal 5-sums: hx[r][c] = sum_{v<5} sx[r][c+v] -------
    // 160 tasks: {x,y} x 40 rows x 2 col-chunks of 18
    if (tid < 160) {
        int arr = tid / 80;
        int rr = tid - arr * 80;
        int r = rr % IN;           // consecutive lanes -> consecutive rows (stride 41: no conflicts)
        int chunk = rr / IN;
        int c0 = chunk * 18;
        const float (*S)[IN + 1] = arr ? sy : sx;
        float (*D)[MID + 1]      = arr ? hy : hx;
        float s = S[r][c0] + S[r][c0 + 1] + S[r][c0 + 2] + S[r][c0 + 3] + S[r][c0 + 4];
        #pragma unroll
        for (int k = 0; k < 18; ++k) {
            D[r][c0 + k] = s;
            if (k != 17) s += S[r][c0 + k + 5] - S[r][c0 + k];
        }
    }
    __syncthreads();

    // ---- Phase 3: vertical 5-sums + center-sub + product -> sp -------------
    // 108 tasks: 36 cols x 3 row-chunks of 12
    if (tid < 108) {
        int b = tid % MID;         // consecutive lanes -> consecutive cols: no conflicts
        int chunk = tid / MID;
        int a0 = chunk * 12;
        float sxs = hx[a0][b] + hx[a0 + 1][b] + hx[a0 + 2][b] + hx[a0 + 3][b] + hx[a0 + 4][b];
        float sys = hy[a0][b] + hy[a0 + 1][b] + hy[a0 + 2][b] + hy[a0 + 3][b] + hy[a0 + 4][b];
        #pragma unroll
        for (int k = 0; k < 12; ++k) {
            int a = a0 + k;
            float xc = sx[a + 2][b + 2] - sxs * (1.f / 25.f);
            float yc = sy[a + 2][b + 2] - sys * (1.f / 25.f);
            sp[a][b] = xc * yc;
            if (k != 11) {
                sxs += hx[a + 5][b] - hx[a][b];
                sys += hy[a + 5][b] - hy[a][b];
            }
        }
    }
    __syncthreads();

    // ---- Phase 4: horizontal 5-sums of p: hp[a][c] = sum_{e<5} sp[a][c+e] --
    // 72 tasks: 36 rows x 2 col-chunks of 16
    if (tid < 72) {
        int r = tid % MID;         // consecutive lanes -> consecutive rows (stride 37: no conflicts)
        int chunk = tid / MID;
        int c0 = chunk * 16;
        float s = sp[r][c0] + sp[r][c0 + 1] + sp[r][c0 + 2] + sp[r][c0 + 3] + sp[r][c0 + 4];
        #pragma unroll
        for (int k = 0; k < 16; ++k) {
            hp[r][c0 + k] = s;
            if (k != 15) s += sp[r][c0 + k + 5] - sp[r][c0 + k];
        }
    }
    __syncthreads();

    // ---- Phase 5: vertical 5-sums of hp -> output (scaled by 1/25) ---------
    // 128 tasks: 32 cols x 4 row-chunks of 8 (lanes cover cols -> coalesced STG)
    if (tid < 128) {
        int j = tid % TILE;
        int chunk = tid / TILE;
        int a0 = chunk * 8;
        float s = hp[a0][j] + hp[a0 + 1][j] + hp[a0 + 2][j] + hp[a0 + 3][j] + hp[a0 + 4][j];
        float* ob = out + (long)blockIdx.z * (long)(OH * OW);
        #pragma unroll
        for (int k = 0; k < 8; ++k) {
            int i = a0 + k;
            int oi = i0 + i, oj = j0 + j;
            if (oi < OH && oj < OW)
                ob[oi * OW + oj] = s * (1.f / 25.f);
            if (k != 7) s += hp[i + 5][j] - hp[i][j];
        }
    }
}

extern "C" void kernel_launch(void* const* d_in, const int* in_sizes, int n_in,
                              void* d_out, int out_size)
{
    (void)in_sizes; (void)n_in; (void)out_size;
    const float* x = (const float*)d_in[0];
    const float* y = (const float*)d_in[1];
    float* out = (float*)d_out;

    dim3 grid((OW + TILE - 1) / TILE, (OH + TILE - 1) / TILE, NB);
    cov_kernel<<<grid, 256>>>(x, y, out);
}

// round 4
// speedup vs baseline: 1.5218x; 1.5218x over previous
#include <cuda_runtime.h>

// Local covariance, fully register-resident streaming design.
// out = boxmean5( (center(x)-boxmean5(x)) * (center(y)-boxmean5(y)) )
// x,y: [16,1,1024,1024] f32 -> out: [16,1,1016,1016] f32
//
// One warp owns a 32-wide raw column strip (24 valid output columns) and
// streams down rows. Vertical 5-window sums are running register sums with
// 5-deep register ring buffers; horizontal 5-sums use 3 warp shuffles.
// No shared memory, no __syncthreads.

#define H  1024
#define W  1024
#define OH 1016
#define OW 1016
#define NB 16

#define CPW      24          // valid output columns per warp
#define NCSTRIP  43          // ceil(1016/24)
#define ROWSTRIP 127         // output rows per warp strip (8 strips * 127 = 1016)
#define ROWS_IN  (ROWSTRIP + 8)   // 135 input rows per strip (= 27 * 5)

__device__ __forceinline__ float hsum5(float v)
{
    // lanes L: v[L]+v[L+1]+v[L+2]+v[L+3]+v[L+4]  (3 shuffles)
    float t = v + __shfl_down_sync(0xffffffffu, v, 1);
    t = t + __shfl_down_sync(0xffffffffu, t, 2);
    return t + __shfl_down_sync(0xffffffffu, v, 4);
}

__global__ __launch_bounds__(128)
void cov_kernel(const float* __restrict__ x,
                const float* __restrict__ y,
                float* __restrict__ out)
{
    const int lane = threadIdx.x & 31;
    const int wrp  = threadIdx.x >> 5;

    const int cs = blockIdx.x;                 // column strip 0..42
    const int rs = blockIdx.y * 4 + wrp;       // row strip 0..7
    const int b  = blockIdx.z;

    const int c  = cs * CPW + lane;            // raw/out column this lane owns
    const int r0 = rs * ROWSTRIP;              // first input row of strip

    const float* __restrict__ xb = x + (long)b * (H * W);
    const float* __restrict__ yb = y + (long)b * (H * W);
    float*       __restrict__ ob = out + (long)b * (OH * OW);

    const bool cok   = (c < W);
    const bool sok   = (lane < CPW) && (c < OW);
    const float inv25 = 1.0f / 25.0f;

    // register ring buffers (constant-indexed inside unrolled phase loop)
    float xr[5]  = {0, 0, 0, 0, 0};
    float yr[5]  = {0, 0, 0, 0, 0};
    float hpr[5] = {0, 0, 0, 0, 0};
    float vsx = 0.f, vsy = 0.f, vhp = 0.f;

    const float* xp = xb + (long)r0 * W + c;
    const float* yp = yb + (long)r0 * W + c;

    for (int rr = 0; rr < ROWS_IN; rr += 5) {
        #pragma unroll
        for (int ph = 0; ph < 5; ++ph) {
            const int rrp = rr + ph;

            // ---- load input row r = r0 + rrp (coalesced, predicated on col) ----
            float xv = cok ? __ldg(xp) : 0.f;
            float yv = cok ? __ldg(yp) : 0.f;
            xp += W; yp += W;

            // ---- vertical running 5-sums of raw columns ----
            vsx += xv - xr[ph]; xr[ph] = xv;
            vsy += yv - yr[ph]; yr[ph] = yv;

            // ---- horizontal 5-sums -> 5x5 box sums at mid row a = rrp-4 ----
            float bx = hsum5(vsx);
            float by = hsum5(vsy);

            // center pixel x[a+2][b+2] = x[r-2][c+2]: ring slot (ph+3)%5, lane+2
            float cx = __shfl_down_sync(0xffffffffu, xr[(ph + 3) % 5], 2);
            float cy = __shfl_down_sync(0xffffffffu, yr[(ph + 3) % 5], 2);

            float pc = (cx - bx * inv25) * (cy - by * inv25);

            // ---- horizontal 5-sum of p, gated until first box is complete ----
            float hp = hsum5(pc);
            hp = (rrp >= 4) ? hp : 0.f;

            // ---- vertical running 5-sum of hp -> output row i = r0 + rrp - 8 ----
            vhp += hp - hpr[ph]; hpr[ph] = hp;

            if (rrp >= 8 && sok) {
                ob[(long)(r0 + rrp - 8) * OW + c] = vhp * inv25;
            }
        }
    }
}

extern "C" void kernel_launch(void* const* d_in, const int* in_sizes, int n_in,
                              void* d_out, int out_size)
{
    (void)in_sizes; (void)n_in; (void)out_size;
    const float* x = (const float*)d_in[0];
    const float* y = (const float*)d_in[1];
    float* out = (float*)d_out;

    dim3 grid(NCSTRIP, 2, NB);   // 43 col strips x (2*4 warps = 8 row strips) x 16 images
    cov_kernel<<<grid, 128>>>(x, y, out);
}

// round 5
// speedup vs baseline: 2.2423x; 1.4734x over previous
#include <cuda_runtime.h>

// Local covariance: out = boxmean5( (center(x)-boxmean5(x)) * (center(y)-boxmean5(y)) )
// x,y: [16,1,1024,1024] f32 -> out: [16,1,1016,1016] f32
//
// Register-resident streaming, 4 columns per lane (float4).
// One warp owns 128 raw columns (120 valid outputs) and streams down rows.
// Vertical 5-sums: running register sums + 5-deep register rings.
// Horizontal 5-sums: in-register sliding sums + one distance-1 shuffle per reg.
// No shared memory, no __syncthreads.

#define H  1024
#define W  1024
#define OH 1016
#define OW 1016
#define NB 16

#define CPWARP 120            // valid output cols per warp (128 raw - 8 halo)
#define NCS    9              // ceil(1016/120)
#define ORS    67             // output rows per strip
#define IRS    75             // input rows per strip (= ORS + 8, multiple of 5)
#define NRS    16             // 16*67 = 1072 >= 1016

__global__ __launch_bounds__(128, 4)
void cov_kernel(const float* __restrict__ x,
                const float* __restrict__ y,
                float* __restrict__ out)
{
    const int lane = threadIdx.x & 31;
    const int wrp  = threadIdx.x >> 5;

    const int cs = blockIdx.x;               // column strip 0..8
    const int rs = blockIdx.y * 4 + wrp;     // row strip 0..15
    const int b  = blockIdx.z;

    const int B  = cs * CPWARP;              // first raw col of warp
    const int c0 = B + lane * 4;             // first raw col of lane
    const int r0 = rs * ORS;                 // first input row of strip

    const float* __restrict__ xb = x + (long)b * (H * W);
    const float* __restrict__ yb = y + (long)b * (H * W);
    float*       __restrict__ ob = out + (long)b * (OH * OW);

    const bool colok = (c0 < W);                      // full float4 load valid
    const bool outok = (lane < 30) && (c0 < OW);      // full float4 store valid
    const float inv25 = 1.0f / 25.0f;

    // register ring buffers (constant-indexed in unrolled phase loop)
    float xr[5][4], yr[5][4], hpr[5][4];
    float vsx[4], vsy[4], vhp[4];
    #pragma unroll
    for (int s = 0; s < 5; ++s)
        #pragma unroll
        for (int i = 0; i < 4; ++i) { xr[s][i] = 0.f; yr[s][i] = 0.f; hpr[s][i] = 0.f; }
    #pragma unroll
    for (int i = 0; i < 4; ++i) { vsx[i] = 0.f; vsy[i] = 0.f; vhp[i] = 0.f; }

    const float4* xp = (const float4*)(xb + (long)r0 * W) + (c0 >> 2);
    const float4* yp = (const float4*)(yb + (long)r0 * W) + (c0 >> 2);

    for (int rr = 0; rr < IRS; rr += 5) {
        #pragma unroll
        for (int ph = 0; ph < 5; ++ph) {
            const int rrp = rr + ph;
            const bool rok = (r0 + rrp) < H;

            float4 xv, yv;
            if (rok && colok) { xv = __ldg(xp); yv = __ldg(yp); }
            else { xv = make_float4(0.f, 0.f, 0.f, 0.f); yv = make_float4(0.f, 0.f, 0.f, 0.f); }
            xp += W / 4; yp += W / 4;

            float xa[4] = {xv.x, xv.y, xv.z, xv.w};
            float ya[4] = {yv.x, yv.y, yv.z, yv.w};

            // ---- vertical running 5-sums of raw columns ----
            #pragma unroll
            for (int i = 0; i < 4; ++i) {
                vsx[i] += xa[i] - xr[ph][i]; xr[ph][i] = xa[i];
                vsy[i] += ya[i] - yr[ph][i]; yr[ph][i] = ya[i];
            }

            // ---- horizontal 5-sums of vertical sums -> 5x5 box sums ----
            float nx[4], ny[4];
            #pragma unroll
            for (int i = 0; i < 4; ++i) {
                nx[i] = __shfl_down_sync(0xffffffffu, vsx[i], 1);
                ny[i] = __shfl_down_sync(0xffffffffu, vsy[i], 1);
            }
            float bx[4], by[4];
            {
                float t = (vsx[0] + vsx[1]) + (vsx[2] + vsx[3]);
                bx[0] = t + nx[0];
                bx[1] = bx[0] - vsx[0] + nx[1];
                bx[2] = bx[1] - vsx[1] + nx[2];
                bx[3] = bx[2] - vsx[2] + nx[3];
                t = (vsy[0] + vsy[1]) + (vsy[2] + vsy[3]);
                by[0] = t + ny[0];
                by[1] = by[0] - vsy[0] + ny[1];
                by[2] = by[1] - vsy[1] + ny[2];
                by[3] = by[2] - vsy[2] + ny[3];
            }

            // ---- center pixels: row rrp-2 (ring slot (ph+3)%5), col u+2 ----
            const int s = (ph + 3) % 5;
            float cx[4], cy[4];
            cx[0] = xr[s][2]; cx[1] = xr[s][3];
            cx[2] = __shfl_down_sync(0xffffffffu, xr[s][0], 1);
            cx[3] = __shfl_down_sync(0xffffffffu, xr[s][1], 1);
            cy[0] = yr[s][2]; cy[1] = yr[s][3];
            cy[2] = __shfl_down_sync(0xffffffffu, yr[s][0], 1);
            cy[3] = __shfl_down_sync(0xffffffffu, yr[s][1], 1);

            float pc[4];
            #pragma unroll
            for (int i = 0; i < 4; ++i)
                pc[i] = (cx[i] - bx[i] * inv25) * (cy[i] - by[i] * inv25);

            // ---- horizontal 5-sum of p ----
            float np[4];
            #pragma unroll
            for (int i = 0; i < 4; ++i)
                np[i] = __shfl_down_sync(0xffffffffu, pc[i], 1);

            float hp0, hp1, hp2, hp3;
            {
                float t = (pc[0] + pc[1]) + (pc[2] + pc[3]);
                hp0 = t + np[0];
                hp1 = hp0 - pc[0] + np[1];
                hp2 = hp1 - pc[1] + np[2];
                hp3 = hp2 - pc[2] + np[3];
            }
            if (rrp < 4) { hp0 = 0.f; hp1 = 0.f; hp2 = 0.f; hp3 = 0.f; }

            // ---- vertical running 5-sum of hp -> output row r0+rrp-8 ----
            vhp[0] += hp0 - hpr[ph][0]; hpr[ph][0] = hp0;
            vhp[1] += hp1 - hpr[ph][1]; hpr[ph][1] = hp1;
            vhp[2] += hp2 - hpr[ph][2]; hpr[ph][2] = hp2;
            vhp[3] += hp3 - hpr[ph][3]; hpr[ph][3] = hp3;

            if (rrp >= 8) {
                const int orow = r0 + rrp - 8;
                if (outok && orow < OH) {
                    float4 o = make_float4(vhp[0] * inv25, vhp[1] * inv25,
                                           vhp[2] * inv25, vhp[3] * inv25);
                    *(float4*)(ob + (long)orow * OW + c0) = o;
                }
            }
        }
    }
}

extern "C" void kernel_launch(void* const* d_in, const int* in_sizes, int n_in,
                              void* d_out, int out_size)
{
    (void)in_sizes; (void)n_in; (void)out_size;
    const float* x = (const float*)d_in[0];
    const float* y = (const float*)d_in[1];
    float* out = (float*)d_out;

    dim3 grid(NCS, NRS / 4, NB);   // 9 col strips x 16 row strips x 16 images
    cov_kernel<<<grid, 128>>>(x, y, out);
}

// round 6
// speedup vs baseline: 2.3999x; 1.0703x over previous
#include <cuda_runtime.h>

// Local covariance: out = boxmean5( (center(x)-boxmean5(x)) * (center(y)-boxmean5(y)) )
// x,y: [16,1,1024,1024] f32 -> out: [16,1,1016,1016] f32
//
// Register-resident streaming, 4 columns per lane (float4), one-row software
// prefetch so each warp always has the next row's loads in flight while
// computing the current row. Streaming stores (__stcs) keep the output from
// evicting input halo lines in L2.
// No shared memory, no __syncthreads.

#define H  1024
#define W  1024
#define OH 1016
#define OW 1016
#define NB 16

#define CPWARP 120            // valid output cols per warp (128 raw - 8 halo)
#define NCS    9              // ceil(1016/120)
#define ORS    67             // output rows per strip
#define IRS    75             // input rows per strip (= ORS + 8, multiple of 5)
#define NRS    16             // 16*67 = 1072 >= 1016

__global__ __launch_bounds__(128, 4)
void cov_kernel(const float* __restrict__ x,
                const float* __restrict__ y,
                float* __restrict__ out)
{
    const int lane = threadIdx.x & 31;
    const int wrp  = threadIdx.x >> 5;

    const int cs = blockIdx.x;               // column strip 0..8
    const int rs = blockIdx.y * 4 + wrp;     // row strip 0..15
    const int b  = blockIdx.z;

    const int c0 = cs * CPWARP + lane * 4;   // first raw col of lane
    const int r0 = rs * ORS;                 // first input row of strip

    const float* __restrict__ xb = x + (long)b * (H * W);
    const float* __restrict__ yb = y + (long)b * (H * W);
    float*       __restrict__ ob = out + (long)b * (OH * OW);

    const bool colok = (c0 < W);                      // full float4 load valid
    const bool outok = (lane < 30) && (c0 < OW);      // full float4 store valid
    const float inv25 = 1.0f / 25.0f;

    // register ring buffers (constant-indexed in unrolled phase loop)
    float xr[5][4], yr[5][4], hpr[5][4];
    float vsx[4], vsy[4], vhp[4];
    #pragma unroll
    for (int s = 0; s < 5; ++s)
        #pragma unroll
        for (int i = 0; i < 4; ++i) { xr[s][i] = 0.f; yr[s][i] = 0.f; hpr[s][i] = 0.f; }
    #pragma unroll
    for (int i = 0; i < 4; ++i) { vsx[i] = 0.f; vsy[i] = 0.f; vhp[i] = 0.f; }

    const float4* xp = (const float4*)(xb + (long)r0 * W) + (c0 >> 2);
    const float4* yp = (const float4*)(yb + (long)r0 * W) + (c0 >> 2);

    // ---- prefetch row 0 ----
    float4 fx, fy;
    {
        const bool rok = (r0 < H) && colok;
        if (rok) { fx = __ldg(xp); fy = __ldg(yp); }
        else { fx = make_float4(0.f, 0.f, 0.f, 0.f); fy = make_float4(0.f, 0.f, 0.f, 0.f); }
        xp += W / 4; yp += W / 4;
    }

    for (int rr = 0; rr < IRS; rr += 5) {
        #pragma unroll
        for (int ph = 0; ph < 5; ++ph) {
            const int rrp = rr + ph;

            // ---- consume prefetched row rrp; prefetch row rrp+1 ----
            float xa[4] = {fx.x, fx.y, fx.z, fx.w};
            float ya[4] = {fy.x, fy.y, fy.z, fy.w};
            {
                const bool rok = (r0 + rrp + 1) < H && colok;
                if (rok) { fx = __ldg(xp); fy = __ldg(yp); }
                else { fx = make_float4(0.f, 0.f, 0.f, 0.f); fy = make_float4(0.f, 0.f, 0.f, 0.f); }
                xp += W / 4; yp += W / 4;
            }

            // ---- vertical running 5-sums of raw columns ----
            #pragma unroll
            for (int i = 0; i < 4; ++i) {
                vsx[i] += xa[i] - xr[ph][i]; xr[ph][i] = xa[i];
                vsy[i] += ya[i] - yr[ph][i]; yr[ph][i] = ya[i];
            }

            // ---- horizontal 5-sums of vertical sums -> 5x5 box sums ----
            float nx[4], ny[4];
            #pragma unroll
            for (int i = 0; i < 4; ++i) {
                nx[i] = __shfl_down_sync(0xffffffffu, vsx[i], 1);
                ny[i] = __shfl_down_sync(0xffffffffu, vsy[i], 1);
            }
            float bx[4], by[4];
            {
                float t = (vsx[0] + vsx[1]) + (vsx[2] + vsx[3]);
                bx[0] = t + nx[0];
                bx[1] = bx[0] - vsx[0] + nx[1];
                bx[2] = bx[1] - vsx[1] + nx[2];
                bx[3] = bx[2] - vsx[2] + nx[3];
                t = (vsy[0] + vsy[1]) + (vsy[2] + vsy[3]);
                by[0] = t + ny[0];
                by[1] = by[0] - vsy[0] + ny[1];
                by[2] = by[1] - vsy[1] + ny[2];
                by[3] = by[2] - vsy[2] + ny[3];
            }

            // ---- center pixels: row rrp-2 (ring slot (ph+3)%5), col u+2 ----
            const int s = (ph + 3) % 5;
            float cx[4], cy[4];
            cx[0] = xr[s][2]; cx[1] = xr[s][3];
            cx[2] = __shfl_down_sync(0xffffffffu, xr[s][0], 1);
            cx[3] = __shfl_down_sync(0xffffffffu, xr[s][1], 1);
            cy[0] = yr[s][2]; cy[1] = yr[s][3];
            cy[2] = __shfl_down_sync(0xffffffffu, yr[s][0], 1);
            cy[3] = __shfl_down_sync(0xffffffffu, yr[s][1], 1);

            float pc[4];
            #pragma unroll
            for (int i = 0; i < 4; ++i)
                pc[i] = (cx[i] - bx[i] * inv25) * (cy[i] - by[i] * inv25);

            // ---- horizontal 5-sum of p ----
            float np[4];
            #pragma unroll
            for (int i = 0; i < 4; ++i)
                np[i] = __shfl_down_sync(0xffffffffu, pc[i], 1);

            float hp0, hp1, hp2, hp3;
            {
                float t = (pc[0] + pc[1]) + (pc[2] + pc[3]);
                hp0 = t + np[0];
                hp1 = hp0 - pc[0] + np[1];
                hp2 = hp1 - pc[1] + np[2];
                hp3 = hp2 - pc[2] + np[3];
            }
            if (rrp < 4) { hp0 = 0.f; hp1 = 0.f; hp2 = 0.f; hp3 = 0.f; }

            // ---- vertical running 5-sum of hp -> output row r0+rrp-8 ----
            vhp[0] += hp0 - hpr[ph][0]; hpr[ph][0] = hp0;
            vhp[1] += hp1 - hpr[ph][1]; hpr[ph][1] = hp1;
            vhp[2] += hp2 - hpr[ph][2]; hpr[ph][2] = hp2;
            vhp[3] += hp3 - hpr[ph][3]; hpr[ph][3] = hp3;

            if (rrp >= 8) {
                const int orow = r0 + rrp - 8;
                if (outok && orow < OH) {
                    float4 o = make_float4(vhp[0] * inv25, vhp[1] * inv25,
                                           vhp[2] * inv25, vhp[3] * inv25);
                    __stcs((float4*)(ob + (long)orow * OW + c0), o);
                }
            }
        }
    }
}

extern "C" void kernel_launch(void* const* d_in, const int* in_sizes, int n_in,
                              void* d_out, int out_size)
{
    (void)in_sizes; (void)n_in; (void)out_size;
    const float* x = (const float*)d_in[0];
    const float* y = (const float*)d_in[1];
    float* out = (float*)d_out;

    dim3 grid(NCS, NRS / 4, NB);   // 9 col strips x 16 row strips x 16 images
    cov_kernel<<<grid, 128>>>(x, y, out);
}